// round 4
// baseline (speedup 1.0000x reference)
#include <cuda_runtime.h>

typedef unsigned long long ull;

#define TPB 128

// G_w[m][n] constants, value duplicated into both 32-bit halves for f32x2.
__device__ ull gGd[4 * 81];

// ---------- f32x2 helpers (Blackwell packed fp32) ----------
__device__ __forceinline__ ull ffma2(ull a, ull b, ull c) {
    ull d;
    asm("fma.rn.f32x2 %0, %1, %2, %3;" : "=l"(d) : "l"(a), "l"(b), "l"(c));
    return d;
}
__device__ __forceinline__ ull pk(float lo, float hi) {
    ull r;
    unsigned int l = __float_as_uint(lo), h = __float_as_uint(hi);
    asm("mov.b64 %0, {%1, %2};" : "=l"(r) : "r"(l), "r"(h));
    return r;
}
__device__ __forceinline__ void upk(ull v, float &lo, float &hi) {
    unsigned int l, h;
    asm("mov.b64 {%0, %1}, %2;" : "=r"(l), "=r"(h) : "l"(v));
    lo = __uint_as_float(l);
    hi = __uint_as_float(h);
}

// ============================================================
// Setup kernel (1 block, 128 threads):
// Phase 1: lanes 0..15 of warp 0 each own one COLUMN of the 16x16
//   circuit unitary M in registers (gates are row ops -> lane-local).
// Phase 2 (one warp per wire w, warp-local sync only):
//   A_w[i][j] = sum_k sign_w(k) * Re(conj(M[k,j]) M[k,i])
//   then transform each qubit index-pair into the (1,C,S) basis -> G_w (9x9).
// ============================================================
__global__ void setup_kernel(const float* __restrict__ qw, int nlayers) {
    __shared__ float Mr[16][16];
    __shared__ float Mi[16][16];
    __shared__ float bufA[4][256];
    __shared__ float bufB[4][192];

    const int tid = threadIdx.x;
    const int wid = tid >> 5;
    const int lane = tid & 31;

    if (tid < 16) {
        float mr[16], mi[16];
#pragma unroll
        for (int r = 0; r < 16; r++) { mr[r] = (r == tid) ? 1.0f : 0.0f; mi[r] = 0.0f; }

        for (int l = 0; l < nlayers; l++) {
#pragma unroll
            for (int w = 0; w < 4; w++) {
                float phi = qw[(l * 4 + w) * 3 + 0];
                float th  = qw[(l * 4 + w) * 3 + 1];
                float om  = qw[(l * 4 + w) * 3 + 2];
                float c, s, ca, sa, cb, sb;
                __sincosf(0.5f * th, &s, &c);
                __sincosf(0.5f * (phi + om), &sa, &ca);   // em = (ca, -sa)
                __sincosf(0.5f * (phi - om), &sb, &cb);   // ed = (cb,  sb)
                float g00r =  ca * c, g00i = -sa * c;
                float g01r = -cb * s, g01i = -sb * s;
                float g10r =  cb * s, g10i = -sb * s;
                float g11r =  ca * c, g11i =  sa * c;
                const int mu = 8 >> w;
#pragma unroll
                for (int r = 0; r < 16; r++) {
                    if (r & mu) continue;
                    const int r1 = r | mu;
                    float ar = mr[r],  ai = mi[r];
                    float br = mr[r1], bi = mi[r1];
                    mr[r]  = g00r * ar - g00i * ai + g01r * br - g01i * bi;
                    mi[r]  = g00r * ai + g00i * ar + g01r * bi + g01i * br;
                    mr[r1] = g10r * ar - g10i * ai + g11r * br - g11i * bi;
                    mi[r1] = g10r * ai + g10i * ar + g11r * bi + g11i * br;
                }
            }
#pragma unroll
            for (int w = 0; w < 4; w++) {
                const int cm = 8 >> w;
                const int tm = 8 >> ((w + 1) & 3);
#pragma unroll
                for (int r = 0; r < 16; r++) {
                    if ((r & cm) && !(r & tm)) {
                        const int r2 = r | tm;
                        float t;
                        t = mr[r]; mr[r] = mr[r2]; mr[r2] = t;
                        t = mi[r]; mi[r] = mi[r2]; mi[r2] = t;
                    }
                }
            }
        }
#pragma unroll
        for (int r = 0; r < 16; r++) { Mr[r][tid] = mr[r]; Mi[r][tid] = mi[r]; }
    }
    __syncthreads();

    // ---- Phase 2: each warp handles one wire, warp-local sync only ----
    {
        const int w = wid;
        const int mw = 8 >> w;
        float* bA = bufA[w];
        float* bB = bufB[w];

        for (int e = lane; e < 256; e += 32) {
            int i = e / 16, j = e % 16;
            float sum = 0.0f;
            for (int k = 0; k < 16; k++) {
                float sgn = (k & mw) ? -1.0f : 1.0f;
                sum += sgn * (Mr[k][i] * Mr[k][j] + Mi[k][i] * Mi[k][j]);
            }
            int b0 = 0;
            for (int q = 0; q < 4; q++) {
                int iw = (i >> (3 - q)) & 1;
                int jw = (j >> (3 - q)) & 1;
                b0 = b0 * 4 + (iw * 2 + jw);
            }
            bA[b0] = sum;
        }
        __syncwarp();

        float* bin  = bA;
        float* bout = bB;
        int pre = 1, post = 64;
        for (int q = 0; q < 4; q++) {
            int nout = pre * 3 * post;
            for (int e = lane; e < nout; e += 32) {
                int po = e % post;
                int al = (e / post) % 3;
                int pr2 = e / (post * 3);
                const float* ip = bin + pr2 * 4 * post;
                float v;
                if (al == 0)      v = 0.5f * (ip[0 * post + po] + ip[3 * post + po]);
                else if (al == 1) v = 0.5f * (ip[0 * post + po] - ip[3 * post + po]);
                else              v = 0.5f * (ip[1 * post + po] + ip[2 * post + po]);
                bout[pr2 * 3 * post + al * post + po] = v;
            }
            __syncwarp();
            float* t = bin; bin = bout; bout = t;
            pre *= 3; post /= 4;
        }
        for (int e = lane; e < 81; e += 32) {
            unsigned int bits = __float_as_uint(bin[e]);
            gGd[w * 81 + e] = ((ull)bits << 32) | (ull)bits;
        }
    }
}

// ============================================================
// Main kernel: ONE f32x2-packed sample pair per thread (2 samples),
// high occupancy (64-reg cap, 32 warps/SM) so LDS / RAW latency is
// hidden by TLP instead of in-thread scheduling.
// out[b][w] = sum_{m,n} G_w[m][n] * Q_m * P_n with
//   Q = (1,C0,S0)x(1,C1,S1), P = (1,C2,S2)x(1,C3,S3), contracted on the fly.
// ============================================================
__global__ void __launch_bounds__(TPB, 8) qmain_kernel(
    const float4* __restrict__ xin, float4* __restrict__ xout, int halfB) {
    __shared__ __align__(16) ull sG[4][9][10];   // padded rows (80B) for LDS.128
    for (int i = threadIdx.x; i < 324; i += TPB)
        sG[i / 81][(i / 9) % 9][i % 9] = gGd[i];
    __syncthreads();

    int idx = blockIdx.x * TPB + threadIdx.x;
    if (idx >= halfB) idx = halfB - 1;   // duplicate-safe clamp

    float4 xa = xin[idx];
    float4 xb = xin[idx + halfB];
    float c0a, s0a, c1a, s1a, c2a, s2a, c3a, s3a;
    float c0b, s0b, c1b, s1b, c2b, s2b, c3b, s3b;
    __sincosf(xa.x, &s0a, &c0a);
    __sincosf(xa.y, &s1a, &c1a);
    __sincosf(xa.z, &s2a, &c2a);
    __sincosf(xa.w, &s3a, &c3a);
    __sincosf(xb.x, &s0b, &c0b);
    __sincosf(xb.y, &s1b, &c1b);
    __sincosf(xb.z, &s2b, &c2b);
    __sincosf(xb.w, &s3b, &c3b);
    const ull C0 = pk(c0a, c0b), S0 = pk(s0a, s0b);
    const ull C1 = pk(c1a, c1b), S1 = pk(s1a, s1b);
    const ull C2 = pk(c2a, c2b), S2 = pk(s2a, s2b);
    const ull C3 = pk(c3a, c3b), S3 = pk(s3a, s3b);

    ull outv[4];
    ull acc0, acc1, acc2;

#pragma unroll
    for (int w = 0; w < 4; w++) {
#pragma unroll
        for (int m = 0; m < 9; m++) {
            const ulonglong2* g2 = reinterpret_cast<const ulonglong2*>(&sG[w][m][0]);
            ulonglong2 gA = g2[0];   // g0,g1
            ulonglong2 gB = g2[1];   // g2,g3
            ulonglong2 gC = g2[2];   // g4,g5
            ulonglong2 gD = g2[3];   // g6,g7
            ull g8 = sG[w][m][8];

            // three independent 2-deep chains over P (qubits 2,3)
            ull t0 = ffma2(C3, gA.y, gA.x);
            t0 = ffma2(S3, gB.x, t0);
            ull t1 = ffma2(C3, gC.x, gB.y);
            t1 = ffma2(S3, gC.y, t1);
            ull t2 = ffma2(C3, gD.y, gD.x);
            t2 = ffma2(S3, g8, t2);
            ull r = ffma2(C2, t1, t0);
            r = ffma2(S2, t2, r);

            const int a = m / 3, b = m % 3;
            ull* A = (a == 0) ? &acc0 : (a == 1) ? &acc1 : &acc2;
            if (b == 0)      *A = r;
            else if (b == 1) *A = ffma2(C1, r, *A);
            else             *A = ffma2(S1, r, *A);
        }
        ull o = ffma2(C0, acc1, acc0);
        o = ffma2(S0, acc2, o);
        outv[w] = o;
    }

    float a0, b0v, a1, b1v, a2, b2v, a3, b3v;
    upk(outv[0], a0, b0v);
    upk(outv[1], a1, b1v);
    upk(outv[2], a2, b2v);
    upk(outv[3], a3, b3v);
    xout[idx]         = make_float4(a0, a1, a2, a3);
    xout[idx + halfB] = make_float4(b0v, b1v, b2v, b3v);
}

extern "C" void kernel_launch(void* const* d_in, const int* in_sizes, int n_in,
                              void* d_out, int out_size) {
    // Identify tensors by size: q_weights is tiny (nlayers*4*3), inputs is B*4.
    int xi = 0, wi = 1;
    if (n_in >= 2 && in_sizes[0] < in_sizes[1]) { xi = 1; wi = 0; }
    const float* x  = (const float*)d_in[xi];
    const float* qw = (const float*)d_in[wi];
    int B = in_sizes[xi] / 4;
    int nlayers = in_sizes[wi] / 12;
    int halfB = B / 2;

    setup_kernel<<<1, TPB>>>(qw, nlayers);

    int blocks = (halfB + TPB - 1) / TPB;
    qmain_kernel<<<blocks, TPB>>>((const float4*)x, (float4*)d_out, halfB);
}

// round 5
// speedup vs baseline: 1.0082x; 1.0082x over previous
#include <cuda_runtime.h>

typedef unsigned long long ull;

#define TPB 128

// G_w[m][n] constants, value duplicated into both 32-bit halves for f32x2.
__device__ ull gGd[4 * 81];

// ---------- f32x2 helpers (Blackwell packed fp32) ----------
__device__ __forceinline__ ull ffma2(ull a, ull b, ull c) {
    ull d;
    asm("fma.rn.f32x2 %0, %1, %2, %3;" : "=l"(d) : "l"(a), "l"(b), "l"(c));
    return d;
}
__device__ __forceinline__ ull pk(float lo, float hi) {
    ull r;
    unsigned int l = __float_as_uint(lo), h = __float_as_uint(hi);
    asm("mov.b64 %0, {%1, %2};" : "=l"(r) : "r"(l), "r"(h));
    return r;
}
__device__ __forceinline__ void upk(ull v, float &lo, float &hi) {
    unsigned int l, h;
    asm("mov.b64 {%0, %1}, %2;" : "=r"(l), "=r"(h) : "l"(v));
    lo = __uint_as_float(l);
    hi = __uint_as_float(h);
}

// ============================================================
// Setup kernel (1 block, 128 threads):
// Phase 1: lanes 0..15 of warp 0 each own one COLUMN of the 16x16
//   circuit unitary M in registers (gates are row ops -> lane-local).
// Phase 2 (one warp per wire w, warp-local sync only):
//   A_w[i][j] = sum_k sign_w(k) * Re(conj(M[k,j]) M[k,i])
//   then transform each qubit index-pair into the (1,C,S) basis -> G_w (9x9).
// ============================================================
__global__ void setup_kernel(const float* __restrict__ qw, int nlayers) {
    __shared__ float Mr[16][16];
    __shared__ float Mi[16][16];
    __shared__ float bufA[4][256];
    __shared__ float bufB[4][192];

    const int tid = threadIdx.x;
    const int wid = tid >> 5;
    const int lane = tid & 31;

    if (tid < 16) {
        float mr[16], mi[16];
#pragma unroll
        for (int r = 0; r < 16; r++) { mr[r] = (r == tid) ? 1.0f : 0.0f; mi[r] = 0.0f; }

        for (int l = 0; l < nlayers; l++) {
#pragma unroll
            for (int w = 0; w < 4; w++) {
                float phi = qw[(l * 4 + w) * 3 + 0];
                float th  = qw[(l * 4 + w) * 3 + 1];
                float om  = qw[(l * 4 + w) * 3 + 2];
                float c, s, ca, sa, cb, sb;
                __sincosf(0.5f * th, &s, &c);
                __sincosf(0.5f * (phi + om), &sa, &ca);   // em = (ca, -sa)
                __sincosf(0.5f * (phi - om), &sb, &cb);   // ed = (cb,  sb)
                float g00r =  ca * c, g00i = -sa * c;
                float g01r = -cb * s, g01i = -sb * s;
                float g10r =  cb * s, g10i = -sb * s;
                float g11r =  ca * c, g11i =  sa * c;
                const int mu = 8 >> w;
#pragma unroll
                for (int r = 0; r < 16; r++) {
                    if (r & mu) continue;
                    const int r1 = r | mu;
                    float ar = mr[r],  ai = mi[r];
                    float br = mr[r1], bi = mi[r1];
                    mr[r]  = g00r * ar - g00i * ai + g01r * br - g01i * bi;
                    mi[r]  = g00r * ai + g00i * ar + g01r * bi + g01i * br;
                    mr[r1] = g10r * ar - g10i * ai + g11r * br - g11i * bi;
                    mi[r1] = g10r * ai + g10i * ar + g11r * bi + g11i * br;
                }
            }
#pragma unroll
            for (int w = 0; w < 4; w++) {
                const int cm = 8 >> w;
                const int tm = 8 >> ((w + 1) & 3);
#pragma unroll
                for (int r = 0; r < 16; r++) {
                    if ((r & cm) && !(r & tm)) {
                        const int r2 = r | tm;
                        float t;
                        t = mr[r]; mr[r] = mr[r2]; mr[r2] = t;
                        t = mi[r]; mi[r] = mi[r2]; mi[r2] = t;
                    }
                }
            }
        }
#pragma unroll
        for (int r = 0; r < 16; r++) { Mr[r][tid] = mr[r]; Mi[r][tid] = mi[r]; }
    }
    __syncthreads();

    // ---- Phase 2: each warp handles one wire, warp-local sync only ----
    {
        const int w = wid;
        const int mw = 8 >> w;
        float* bA = bufA[w];
        float* bB = bufB[w];

        for (int e = lane; e < 256; e += 32) {
            int i = e / 16, j = e % 16;
            float sum = 0.0f;
            for (int k = 0; k < 16; k++) {
                float sgn = (k & mw) ? -1.0f : 1.0f;
                sum += sgn * (Mr[k][i] * Mr[k][j] + Mi[k][i] * Mi[k][j]);
            }
            int b0 = 0;
            for (int q = 0; q < 4; q++) {
                int iw = (i >> (3 - q)) & 1;
                int jw = (j >> (3 - q)) & 1;
                b0 = b0 * 4 + (iw * 2 + jw);
            }
            bA[b0] = sum;
        }
        __syncwarp();

        float* bin  = bA;
        float* bout = bB;
        int pre = 1, post = 64;
        for (int q = 0; q < 4; q++) {
            int nout = pre * 3 * post;
            for (int e = lane; e < nout; e += 32) {
                int po = e % post;
                int al = (e / post) % 3;
                int pr2 = e / (post * 3);
                const float* ip = bin + pr2 * 4 * post;
                float v;
                if (al == 0)      v = 0.5f * (ip[0 * post + po] + ip[3 * post + po]);
                else if (al == 1) v = 0.5f * (ip[0 * post + po] - ip[3 * post + po]);
                else              v = 0.5f * (ip[1 * post + po] + ip[2 * post + po]);
                bout[pr2 * 3 * post + al * post + po] = v;
            }
            __syncwarp();
            float* t = bin; bin = bout; bout = t;
            pre *= 3; post /= 4;
        }
        for (int e = lane; e < 81; e += 32) {
            unsigned int bits = __float_as_uint(bin[e]);
            gGd[w * 81 + e] = ((ull)bits << 32) | (ull)bits;
        }
    }
}

// ============================================================
// Main kernel: ONE f32x2-packed sample pair per thread (2 samples),
// high occupancy (64-reg cap, 32 warps/SM) so LDS / RAW latency is
// hidden by TLP instead of in-thread scheduling.
// out[b][w] = sum_{m,n} G_w[m][n] * Q_m * P_n with
//   Q = (1,C0,S0)x(1,C1,S1), P = (1,C2,S2)x(1,C3,S3), contracted on the fly.
// ============================================================
__global__ void __launch_bounds__(TPB, 8) qmain_kernel(
    const float4* __restrict__ xin, float4* __restrict__ xout, int halfB) {
    __shared__ __align__(16) ull sG[4][9][10];   // padded rows (80B) for LDS.128
    for (int i = threadIdx.x; i < 324; i += TPB)
        sG[i / 81][(i / 9) % 9][i % 9] = gGd[i];
    __syncthreads();

    int idx = blockIdx.x * TPB + threadIdx.x;
    if (idx >= halfB) idx = halfB - 1;   // duplicate-safe clamp

    float4 xa = xin[idx];
    float4 xb = xin[idx + halfB];
    float c0a, s0a, c1a, s1a, c2a, s2a, c3a, s3a;
    float c0b, s0b, c1b, s1b, c2b, s2b, c3b, s3b;
    __sincosf(xa.x, &s0a, &c0a);
    __sincosf(xa.y, &s1a, &c1a);
    __sincosf(xa.z, &s2a, &c2a);
    __sincosf(xa.w, &s3a, &c3a);
    __sincosf(xb.x, &s0b, &c0b);
    __sincosf(xb.y, &s1b, &c1b);
    __sincosf(xb.z, &s2b, &c2b);
    __sincosf(xb.w, &s3b, &c3b);
    const ull C0 = pk(c0a, c0b), S0 = pk(s0a, s0b);
    const ull C1 = pk(c1a, c1b), S1 = pk(s1a, s1b);
    const ull C2 = pk(c2a, c2b), S2 = pk(s2a, s2b);
    const ull C3 = pk(c3a, c3b), S3 = pk(s3a, s3b);

    ull outv[4];
    ull acc0, acc1, acc2;

#pragma unroll
    for (int w = 0; w < 4; w++) {
#pragma unroll
        for (int m = 0; m < 9; m++) {
            const ulonglong2* g2 = reinterpret_cast<const ulonglong2*>(&sG[w][m][0]);
            ulonglong2 gA = g2[0];   // g0,g1
            ulonglong2 gB = g2[1];   // g2,g3
            ulonglong2 gC = g2[2];   // g4,g5
            ulonglong2 gD = g2[3];   // g6,g7
            ull g8 = sG[w][m][8];

            // three independent 2-deep chains over P (qubits 2,3)
            ull t0 = ffma2(C3, gA.y, gA.x);
            t0 = ffma2(S3, gB.x, t0);
            ull t1 = ffma2(C3, gC.x, gB.y);
            t1 = ffma2(S3, gC.y, t1);
            ull t2 = ffma2(C3, gD.y, gD.x);
            t2 = ffma2(S3, g8, t2);
            ull r = ffma2(C2, t1, t0);
            r = ffma2(S2, t2, r);

            const int a = m / 3, b = m % 3;
            ull* A = (a == 0) ? &acc0 : (a == 1) ? &acc1 : &acc2;
            if (b == 0)      *A = r;
            else if (b == 1) *A = ffma2(C1, r, *A);
            else             *A = ffma2(S1, r, *A);
        }
        ull o = ffma2(C0, acc1, acc0);
        o = ffma2(S0, acc2, o);
        outv[w] = o;
    }

    float a0, b0v, a1, b1v, a2, b2v, a3, b3v;
    upk(outv[0], a0, b0v);
    upk(outv[1], a1, b1v);
    upk(outv[2], a2, b2v);
    upk(outv[3], a3, b3v);
    xout[idx]         = make_float4(a0, a1, a2, a3);
    xout[idx + halfB] = make_float4(b0v, b1v, b2v, b3v);
}

extern "C" void kernel_launch(void* const* d_in, const int* in_sizes, int n_in,
                              void* d_out, int out_size) {
    // Identify tensors by size: q_weights is tiny (nlayers*4*3), inputs is B*4.
    int xi = 0, wi = 1;
    if (n_in >= 2 && in_sizes[0] < in_sizes[1]) { xi = 1; wi = 0; }
    const float* x  = (const float*)d_in[xi];
    const float* qw = (const float*)d_in[wi];
    int B = in_sizes[xi] / 4;
    int nlayers = in_sizes[wi] / 12;
    int halfB = B / 2;

    setup_kernel<<<1, TPB>>>(qw, nlayers);

    int blocks = (halfB + TPB - 1) / TPB;
    qmain_kernel<<<blocks, TPB>>>((const float4*)x, (float4*)d_out, halfB);
}

// round 6
// speedup vs baseline: 1.1606x; 1.1511x over previous
#include <cuda_runtime.h>

typedef unsigned long long ull;

#define TPB 128

// G_w[m][n] constants, value duplicated into both 32-bit halves for f32x2.
__device__ ull gGd[4 * 81];

// ---------- f32x2 helpers (Blackwell packed fp32) ----------
__device__ __forceinline__ ull ffma2(ull a, ull b, ull c) {
    ull d;
    asm("fma.rn.f32x2 %0, %1, %2, %3;" : "=l"(d) : "l"(a), "l"(b), "l"(c));
    return d;
}
__device__ __forceinline__ ull pk(float lo, float hi) {
    ull r;
    unsigned int l = __float_as_uint(lo), h = __float_as_uint(hi);
    asm("mov.b64 %0, {%1, %2};" : "=l"(r) : "r"(l), "r"(h));
    return r;
}
__device__ __forceinline__ void upk(ull v, float &lo, float &hi) {
    unsigned int l, h;
    asm("mov.b64 {%0, %1}, %2;" : "=r"(l), "=r"(h) : "l"(v));
    lo = __uint_as_float(l);
    hi = __uint_as_float(h);
}

// ============================================================
// Setup kernel (1 block, 128 threads):
// Phase 1: lanes 0..15 of warp 0 each own one COLUMN of the 16x16
//   circuit unitary M in registers (gates are row ops -> lane-local).
// Phase 2 (one warp per wire w, warp-local sync only):
//   A_w[i][j] = sum_k sign_w(k) * Re(conj(M[k,j]) M[k,i])
//   then transform each qubit index-pair into the (1,C,S) basis -> G_w (9x9).
// ============================================================
__global__ void setup_kernel(const float* __restrict__ qw, int nlayers) {
    __shared__ float Mr[16][16];
    __shared__ float Mi[16][16];
    __shared__ float bufA[4][256];
    __shared__ float bufB[4][192];

    const int tid = threadIdx.x;
    const int wid = tid >> 5;
    const int lane = tid & 31;

    if (tid < 16) {
        float mr[16], mi[16];
#pragma unroll
        for (int r = 0; r < 16; r++) { mr[r] = (r == tid) ? 1.0f : 0.0f; mi[r] = 0.0f; }

        for (int l = 0; l < nlayers; l++) {
#pragma unroll
            for (int w = 0; w < 4; w++) {
                float phi = qw[(l * 4 + w) * 3 + 0];
                float th  = qw[(l * 4 + w) * 3 + 1];
                float om  = qw[(l * 4 + w) * 3 + 2];
                float c, s, ca, sa, cb, sb;
                __sincosf(0.5f * th, &s, &c);
                __sincosf(0.5f * (phi + om), &sa, &ca);   // em = (ca, -sa)
                __sincosf(0.5f * (phi - om), &sb, &cb);   // ed = (cb,  sb)
                float g00r =  ca * c, g00i = -sa * c;
                float g01r = -cb * s, g01i = -sb * s;
                float g10r =  cb * s, g10i = -sb * s;
                float g11r =  ca * c, g11i =  sa * c;
                const int mu = 8 >> w;
#pragma unroll
                for (int r = 0; r < 16; r++) {
                    if (r & mu) continue;
                    const int r1 = r | mu;
                    float ar = mr[r],  ai = mi[r];
                    float br = mr[r1], bi = mi[r1];
                    mr[r]  = g00r * ar - g00i * ai + g01r * br - g01i * bi;
                    mi[r]  = g00r * ai + g00i * ar + g01r * bi + g01i * br;
                    mr[r1] = g10r * ar - g10i * ai + g11r * br - g11i * bi;
                    mi[r1] = g10r * ai + g10i * ar + g11r * bi + g11i * br;
                }
            }
#pragma unroll
            for (int w = 0; w < 4; w++) {
                const int cm = 8 >> w;
                const int tm = 8 >> ((w + 1) & 3);
#pragma unroll
                for (int r = 0; r < 16; r++) {
                    if ((r & cm) && !(r & tm)) {
                        const int r2 = r | tm;
                        float t;
                        t = mr[r]; mr[r] = mr[r2]; mr[r2] = t;
                        t = mi[r]; mi[r] = mi[r2]; mi[r2] = t;
                    }
                }
            }
        }
#pragma unroll
        for (int r = 0; r < 16; r++) { Mr[r][tid] = mr[r]; Mi[r][tid] = mi[r]; }
    }
    __syncthreads();

    // ---- Phase 2: each warp handles one wire, warp-local sync only ----
    {
        const int w = wid;
        const int mw = 8 >> w;
        float* bA = bufA[w];
        float* bB = bufB[w];

        for (int e = lane; e < 256; e += 32) {
            int i = e / 16, j = e % 16;
            float sum = 0.0f;
            for (int k = 0; k < 16; k++) {
                float sgn = (k & mw) ? -1.0f : 1.0f;
                sum += sgn * (Mr[k][i] * Mr[k][j] + Mi[k][i] * Mi[k][j]);
            }
            int b0 = 0;
            for (int q = 0; q < 4; q++) {
                int iw = (i >> (3 - q)) & 1;
                int jw = (j >> (3 - q)) & 1;
                b0 = b0 * 4 + (iw * 2 + jw);
            }
            bA[b0] = sum;
        }
        __syncwarp();

        float* bin  = bA;
        float* bout = bB;
        int pre = 1, post = 64;
        for (int q = 0; q < 4; q++) {
            int nout = pre * 3 * post;
            for (int e = lane; e < nout; e += 32) {
                int po = e % post;
                int al = (e / post) % 3;
                int pr2 = e / (post * 3);
                const float* ip = bin + pr2 * 4 * post;
                float v;
                if (al == 0)      v = 0.5f * (ip[0 * post + po] + ip[3 * post + po]);
                else if (al == 1) v = 0.5f * (ip[0 * post + po] - ip[3 * post + po]);
                else              v = 0.5f * (ip[1 * post + po] + ip[2 * post + po]);
                bout[pr2 * 3 * post + al * post + po] = v;
            }
            __syncwarp();
            float* t = bin; bin = bout; bout = t;
            pre *= 3; post /= 4;
        }
        for (int e = lane; e < 81; e += 32) {
            unsigned int bits = __float_as_uint(bin[e]);
            gGd[w * 81 + e] = ((ull)bits << 32) | (ull)bits;
        }
    }
}

// ============================================================
// Main kernel: TWO f32x2-packed sample pairs per thread (4 samples) so
// each broadcast G-row LDS is amortized over 4 samples (keeps L1 pipe
// under the fma pipe), with a tight register budget (scalar per-wire
// stores, no result arrays) so occupancy stays ~7 warps/SMSP.
// out[b][w] = sum_{m,n} G_w[m][n] * Q_m * P_n with
//   Q = (1,C0,S0)x(1,C1,S1), P = (1,C2,S2)x(1,C3,S3), contracted on the fly.
// ============================================================
__global__ void __launch_bounds__(TPB, 7) qmain_kernel(
    const float4* __restrict__ xin, float* __restrict__ xout, int halfB) {
    __shared__ __align__(16) ull sG[4][9][10];   // padded rows (80B) for LDS.128
    for (int i = threadIdx.x; i < 324; i += TPB)
        sG[i / 81][(i / 9) % 9][i % 9] = gGd[i];
    __syncthreads();

    const int base = blockIdx.x * (TPB * 2) + threadIdx.x;

    ull C0[2], S0[2], C1[2], S1[2], C2[2], S2[2], C3[2], S3[2];
    int idxs[2];

#pragma unroll
    for (int p = 0; p < 2; p++) {
        int idx = base + p * TPB;
        if (idx >= halfB) idx = halfB - 1;   // duplicate-safe clamp
        idxs[p] = idx;
        float4 xa = xin[idx];
        float4 xb = xin[idx + halfB];
        float c0a, s0a, c1a, s1a, c2a, s2a, c3a, s3a;
        float c0b, s0b, c1b, s1b, c2b, s2b, c3b, s3b;
        __sincosf(xa.x, &s0a, &c0a);
        __sincosf(xa.y, &s1a, &c1a);
        __sincosf(xa.z, &s2a, &c2a);
        __sincosf(xa.w, &s3a, &c3a);
        __sincosf(xb.x, &s0b, &c0b);
        __sincosf(xb.y, &s1b, &c1b);
        __sincosf(xb.z, &s2b, &c2b);
        __sincosf(xb.w, &s3b, &c3b);
        C0[p] = pk(c0a, c0b);  S0[p] = pk(s0a, s0b);
        C1[p] = pk(c1a, c1b);  S1[p] = pk(s1a, s1b);
        C2[p] = pk(c2a, c2b);  S2[p] = pk(s2a, s2b);
        C3[p] = pk(c3a, c3b);  S3[p] = pk(s3a, s3b);
    }

#pragma unroll
    for (int w = 0; w < 4; w++) {
        ull acc0[2], acc1[2], acc2[2];
#pragma unroll
        for (int m = 0; m < 9; m++) {
            const ulonglong2* g2 = reinterpret_cast<const ulonglong2*>(&sG[w][m][0]);
            ulonglong2 gA = g2[0];   // g0,g1
            ulonglong2 gB = g2[1];   // g2,g3
            ulonglong2 gC = g2[2];   // g4,g5
            ulonglong2 gD = g2[3];   // g6,g7
            ull g8 = sG[w][m][8];
            const int a = m / 3, b = m % 3;
#pragma unroll
            for (int p = 0; p < 2; p++) {
                // three independent 2-deep chains over P (qubits 2,3)
                ull t0 = ffma2(C3[p], gA.y, gA.x);
                t0 = ffma2(S3[p], gB.x, t0);
                ull t1 = ffma2(C3[p], gC.x, gB.y);
                t1 = ffma2(S3[p], gC.y, t1);
                ull t2 = ffma2(C3[p], gD.y, gD.x);
                t2 = ffma2(S3[p], g8, t2);
                ull r = ffma2(C2[p], t1, t0);
                r = ffma2(S2[p], t2, r);

                ull* A = (a == 0) ? &acc0[p] : (a == 1) ? &acc1[p] : &acc2[p];
                if (b == 0)      *A = r;
                else if (b == 1) *A = ffma2(C1[p], r, *A);
                else             *A = ffma2(S1[p], r, *A);
            }
        }
        // finish wire w for both pairs; store scalars immediately (no result
        // arrays -> lower register pressure -> higher occupancy)
#pragma unroll
        for (int p = 0; p < 2; p++) {
            ull o = ffma2(C0[p], acc1[p], acc0[p]);
            o = ffma2(S0[p], acc2[p], o);
            float lo, hi;
            upk(o, lo, hi);
            xout[idxs[p] * 4 + w]           = lo;
            xout[(idxs[p] + halfB) * 4 + w] = hi;
        }
    }
}

extern "C" void kernel_launch(void* const* d_in, const int* in_sizes, int n_in,
                              void* d_out, int out_size) {
    // Identify tensors by size: q_weights is tiny (nlayers*4*3), inputs is B*4.
    int xi = 0, wi = 1;
    if (n_in >= 2 && in_sizes[0] < in_sizes[1]) { xi = 1; wi = 0; }
    const float* x  = (const float*)d_in[xi];
    const float* qw = (const float*)d_in[wi];
    int B = in_sizes[xi] / 4;
    int nlayers = in_sizes[wi] / 12;
    int halfB = B / 2;

    setup_kernel<<<1, TPB>>>(qw, nlayers);

    int blocks = (halfB + TPB * 2 - 1) / (TPB * 2);
    qmain_kernel<<<blocks, TPB>>>((const float4*)x, (float*)d_out, halfB);
}